// round 15
// baseline (speedup 1.0000x reference)
#include <cuda_runtime.h>
#include <cuda_fp16.h>
#include <cstdint>

// SiteWiseLSTM (sm_103a) — round 11: pipelined HMMA, spill-free.
// Round-10 window structure (epilogue always overlapped with an independent
// MMA stream), but TH=512 with warp = (m-pair, sample-half): each warp does
// 2 m-tiles x 4 n-tiles, so each accumulator set is 32 regs (d0+d1 = 128
// fixed regs, no spill; round-10's 192 spilled). occ 4 warps/SMSP.
//   W2(t): epi0(t) [d0 -> h0new]        || L1b(t): d1  = Whh1.h1(t-1)
//   bar
//   W1(t): L1a: d1 += Wih1.h0new; L0(t+1): d0 = Whh0.h0new || epi1(t)
//   bar
// Math identical to round 9: mma.sync m16n8k16, 3-pass hi/lo fp16 split,
// fp32 accum (rel_err ~1.4e-6).

#define TH   512
#define MM   64
#define HID  64
#define LL   168
#define HOR  24
#define SS   512
#define NB   256
#define HSW  72          // row stride in halves (144B, conflict-free)

// SMEM byte offsets
#define WLO0  0          // [256][72] half : Whh0 lo (decoder: Wchh lo)
#define WLO1  36864      // Wih1 lo
#define WLO2  73728      // Whh1 lo
#define WHI   110592     // hi staging; ends holding Whh1 hi (decoder staging)
#define H0HI  147456     // [64][72] half
#define H0LO  156672
#define H1HI  165888
#define H1LO  175104
#define XB    184320     // float[2][64]
#define WOUTS 184832     // float[64]
#define CB0   185088     // float[256] layer0 bias, [u*4+e]
#define CW0   186112     // float[256] Wih0
#define CB1   187136     // float[256] layer1 bias
#define CBC   188160     // float[256] decoder bias
#define CWC   189184     // float[256] Wcih
#define SMEMB 190208

__device__ __forceinline__ uint32_t lh2(const __half* p) {
    return *(const uint32_t*)p;
}
__device__ __forceinline__ float tanha(float x) {
    float y;
    asm("tanh.approx.f32 %0, %1;" : "=f"(y) : "f"(x));
    return y;
}
__device__ __forceinline__ float sigf(float x) {
    return fmaf(0.5f, tanha(0.5f * x), 0.5f);
}
__device__ __forceinline__ void mma16816(float* d, uint32_t a0, uint32_t a1,
                                         uint32_t a2, uint32_t a3,
                                         uint32_t b0, uint32_t b1) {
    asm volatile(
        "mma.sync.aligned.m16n8k16.row.col.f32.f16.f16.f32 "
        "{%0,%1,%2,%3}, {%4,%5,%6,%7}, {%8,%9}, {%0,%1,%2,%3};"
        : "+f"(d[0]), "+f"(d[1]), "+f"(d[2]), "+f"(d[3])
        : "r"(a0), "r"(a1), "r"(a2), "r"(a3), "r"(b0), "r"(b1));
}

// Stage fp32 W[256][64] (rows e*64+u) -> SMEM hi/lo fp16, permuted rows
// r = 32*(u>>3) + 8*e + (u&7), 72-half stride.
__device__ __forceinline__ void stageW(const float* __restrict__ W,
                                       __half* Hi, __half* Lo, int tid) {
    for (int idx = tid; idx < 256 * 64; idx += TH) {
        int row = idx >> 6, k = idx & 63;
        int e = row >> 6, u = row & 63;
        int r = ((u >> 3) << 5) + (e << 3) + (u & 7);
        float w = W[idx];
        __half hi = __float2half_rn(w);
        __half lo = __float2half_rn(w - __half2float(hi));
        Hi[r * HSW + k] = hi;
        Lo[r * HSW + k] = lo;
    }
}

__device__ __forceinline__ void loadfrags(const __half* Hi, uint32_t (&f)[2][4][4],
                                          int jr, int g, int tg) {
#pragma unroll
    for (int m = 0; m < 2; ++m)
#pragma unroll
        for (int kt = 0; kt < 4; ++kt) {
            int r0 = jr + 16 * m + g, r1 = r0 + 8, kb = 16 * kt + 2 * tg;
            f[m][kt][0] = lh2(Hi + r0 * HSW + kb);
            f[m][kt][1] = lh2(Hi + r1 * HSW + kb);
            f[m][kt][2] = lh2(Hi + r0 * HSW + kb + 8);
            f[m][kt][3] = lh2(Hi + r1 * HSW + kb + 8);
        }
}

// d += (Ahi+Alo).(Bhi) + Ahi.(Blo); A hi fragments from registers.
// 4 n-tiles starting at sample row sb.
__device__ __forceinline__ void matphaseR(const uint32_t (&ahi)[2][4][4],
                                          const __half* __restrict__ Alo,
                                          const __half* __restrict__ Bhi,
                                          const __half* __restrict__ Blo,
                                          float (&d)[4][2][4],
                                          int jr, int g, int tg, int sb) {
#pragma unroll
    for (int kt = 0; kt < 4; ++kt) {
        const int kb = 16 * kt + 2 * tg;
        uint32_t alo[2][4];
#pragma unroll
        for (int m = 0; m < 2; ++m) {
            int r0 = jr + 16 * m + g, r1 = r0 + 8;
            alo[m][0] = lh2(Alo + r0 * HSW + kb);
            alo[m][1] = lh2(Alo + r1 * HSW + kb);
            alo[m][2] = lh2(Alo + r0 * HSW + kb + 8);
            alo[m][3] = lh2(Alo + r1 * HSW + kb + 8);
        }
#pragma unroll
        for (int nt = 0; nt < 4; ++nt) {
            const __half* bp = Bhi + (sb + 8 * nt + g) * HSW + kb;
            uint32_t b0 = lh2(bp), b1 = lh2(bp + 8);
            mma16816(d[nt][0], ahi[0][kt][0], ahi[0][kt][1], ahi[0][kt][2], ahi[0][kt][3], b0, b1);
            mma16816(d[nt][1], ahi[1][kt][0], ahi[1][kt][1], ahi[1][kt][2], ahi[1][kt][3], b0, b1);
            mma16816(d[nt][0], alo[0][0], alo[0][1], alo[0][2], alo[0][3], b0, b1);
            mma16816(d[nt][1], alo[1][0], alo[1][1], alo[1][2], alo[1][3], b0, b1);
        }
#pragma unroll
        for (int nt = 0; nt < 4; ++nt) {
            const __half* bp = Blo + (sb + 8 * nt + g) * HSW + kb;
            uint32_t b0 = lh2(bp), b1 = lh2(bp + 8);
            mma16816(d[nt][0], ahi[0][kt][0], ahi[0][kt][1], ahi[0][kt][2], ahi[0][kt][3], b0, b1);
            mma16816(d[nt][1], ahi[1][kt][0], ahi[1][kt][1], ahi[1][kt][2], ahi[1][kt][3], b0, b1);
        }
    }
}

// Same but A hi fragments loaded from SMEM.
__device__ __forceinline__ void matphaseS(const __half* __restrict__ Ahi,
                                          const __half* __restrict__ Alo,
                                          const __half* __restrict__ Bhi,
                                          const __half* __restrict__ Blo,
                                          float (&d)[4][2][4],
                                          int jr, int g, int tg, int sb) {
#pragma unroll
    for (int kt = 0; kt < 4; ++kt) {
        const int kb = 16 * kt + 2 * tg;
        uint32_t ahi[2][4], alo[2][4];
#pragma unroll
        for (int m = 0; m < 2; ++m) {
            int r0 = jr + 16 * m + g, r1 = r0 + 8;
            ahi[m][0] = lh2(Ahi + r0 * HSW + kb);
            ahi[m][1] = lh2(Ahi + r1 * HSW + kb);
            ahi[m][2] = lh2(Ahi + r0 * HSW + kb + 8);
            ahi[m][3] = lh2(Ahi + r1 * HSW + kb + 8);
            alo[m][0] = lh2(Alo + r0 * HSW + kb);
            alo[m][1] = lh2(Alo + r1 * HSW + kb);
            alo[m][2] = lh2(Alo + r0 * HSW + kb + 8);
            alo[m][3] = lh2(Alo + r1 * HSW + kb + 8);
        }
#pragma unroll
        for (int nt = 0; nt < 4; ++nt) {
            const __half* bp = Bhi + (sb + 8 * nt + g) * HSW + kb;
            uint32_t b0 = lh2(bp), b1 = lh2(bp + 8);
            mma16816(d[nt][0], ahi[0][0], ahi[0][1], ahi[0][2], ahi[0][3], b0, b1);
            mma16816(d[nt][1], ahi[1][0], ahi[1][1], ahi[1][2], ahi[1][3], b0, b1);
            mma16816(d[nt][0], alo[0][0], alo[0][1], alo[0][2], alo[0][3], b0, b1);
            mma16816(d[nt][1], alo[1][0], alo[1][1], alo[1][2], alo[1][3], b0, b1);
        }
#pragma unroll
        for (int nt = 0; nt < 4; ++nt) {
            const __half* bp = Blo + (sb + 8 * nt + g) * HSW + kb;
            uint32_t b0 = lh2(bp), b1 = lh2(bp + 8);
            mma16816(d[nt][0], ahi[0][0], ahi[0][1], ahi[0][2], ahi[0][3], b0, b1);
            mma16816(d[nt][1], ahi[1][0], ahi[1][1], ahi[1][2], ahi[1][3], b0, b1);
        }
    }
}

// Cell update + h writeback for 8 cells (4 nt x 2 samples), unit u.
// d[nt][0][0,1]=i  d[nt][0][2,3]=f  d[nt][1][0,1]=g  d[nt][1][2,3]=o
template<bool HASX>
__device__ __forceinline__ void epilayer(float (&d)[4][2][4], float* cst,
                                         const float4* __restrict__ bs4,
                                         const float4* __restrict__ ws4,
                                         const float* __restrict__ xb,
                                         __half* Hhi, __half* Hlo,
                                         int u, int tg, int sb) {
    float4 bb = bs4[u];
    float4 wv = HASX ? ws4[u] : make_float4(0.f, 0.f, 0.f, 0.f);
#pragma unroll
    for (int nt = 0; nt < 4; ++nt) {
        int s0 = sb + 8 * nt + 2 * tg;
        float gi0 = d[nt][0][0] + bb.x, gi1 = d[nt][0][1] + bb.x;
        float gf0 = d[nt][0][2] + bb.y, gf1 = d[nt][0][3] + bb.y;
        float gg0 = d[nt][1][0] + bb.z, gg1 = d[nt][1][1] + bb.z;
        float go0 = d[nt][1][2] + bb.w, go1 = d[nt][1][3] + bb.w;
        if (HASX) {
            float2 xv = *(const float2*)(xb + s0);
            gi0 = fmaf(wv.x, xv.x, gi0); gi1 = fmaf(wv.x, xv.y, gi1);
            gf0 = fmaf(wv.y, xv.x, gf0); gf1 = fmaf(wv.y, xv.y, gf1);
            gg0 = fmaf(wv.z, xv.x, gg0); gg1 = fmaf(wv.z, xv.y, gg1);
            go0 = fmaf(wv.w, xv.x, go0); go1 = fmaf(wv.w, xv.y, go1);
        }
        float nc0 = sigf(gf0) * cst[2 * nt]     + sigf(gi0) * tanha(gg0);
        float nc1 = sigf(gf1) * cst[2 * nt + 1] + sigf(gi1) * tanha(gg1);
        cst[2 * nt] = nc0; cst[2 * nt + 1] = nc1;
        float h0 = sigf(go0) * tanha(nc0);
        float h1 = sigf(go1) * tanha(nc1);
        __half hh0 = __float2half_rn(h0);
        __half hh1 = __float2half_rn(h1);
        Hhi[s0 * HSW + u] = hh0;
        Hlo[s0 * HSW + u] = __float2half_rn(h0 - __half2float(hh0));
        Hhi[(s0 + 1) * HSW + u] = hh1;
        Hlo[(s0 + 1) * HSW + u] = __float2half_rn(h1 - __half2float(hh1));
    }
}

__global__ void __launch_bounds__(TH, 1)
lstm_mma_kernel(const float* __restrict__ X,
                const float* __restrict__ Wih0, const float* __restrict__ Whh0,
                const float* __restrict__ bih0, const float* __restrict__ bhh0,
                const float* __restrict__ Wih1, const float* __restrict__ Whh1,
                const float* __restrict__ bih1, const float* __restrict__ bhh1,
                const float* __restrict__ Wcih, const float* __restrict__ Wchh,
                const float* __restrict__ bcih, const float* __restrict__ bchh,
                const float* __restrict__ Wout, const float* __restrict__ bout,
                float* __restrict__ out) {
    extern __shared__ char sm[];
    __half* wlo0 = (__half*)(sm + WLO0);
    __half* wlo1 = (__half*)(sm + WLO1);
    __half* wlo2 = (__half*)(sm + WLO2);
    __half* whi  = (__half*)(sm + WHI);
    __half* h0hi = (__half*)(sm + H0HI);
    __half* h0lo = (__half*)(sm + H0LO);
    __half* h1hi = (__half*)(sm + H1HI);
    __half* h1lo = (__half*)(sm + H1LO);
    float* xbuf  = (float*)(sm + XB);
    float* wouts = (float*)(sm + WOUTS);
    const float4* cb0 = (const float4*)(sm + CB0);
    const float4* cw0 = (const float4*)(sm + CW0);
    const float4* cb1 = (const float4*)(sm + CB1);
    const float4* cbc = (const float4*)(sm + CBC);
    const float4* cwc = (const float4*)(sm + CWC);

    const int tid = threadIdx.x;
    const int lane = tid & 31;
    const int warp = tid >> 5;        // 0..15
    const int j = warp & 7;           // m-pair
    const int half = warp >> 3;       // sample half
    const int sb = half * 32;         // sample base row
    const int g = lane >> 2;
    const int tg = lane & 3;
    const int jr = 32 * j;
    const int u = 8 * j + g;

    const int n0 = blockIdx.x * MM;
    const int b  = n0 >> 9;
    const int s0blk = n0 & (SS - 1);
    const long xrow = (long)b * LL * SS + s0blk;

    uint32_t aW0[2][4][4], aW1i[2][4][4];

    // ---- stage weights: hi via WHI (frags for Whh0/Wih1; Whh1 hi stays) ----
    stageW(Whh0, whi, wlo0, tid);
    __syncthreads();
    loadfrags(whi, aW0, jr, g, tg);
    __syncthreads();
    stageW(Wih1, whi, wlo1, tid);
    __syncthreads();
    loadfrags(whi, aW1i, jr, g, tg);
    __syncthreads();
    stageW(Whh1, whi, wlo2, tid);          // hi stays in SMEM for L1b

    // zero h arrays, stage constants / x(0) / wout
    for (int idx = tid; idx < (4 * 9216) / 4; idx += TH)
        ((uint32_t*)(sm + H0HI))[idx] = 0;
    for (int jx = tid; jx < 256; jx += TH) {
        int e = jx >> 6, uu = jx & 63, n = uu * 4 + e;
        ((float*)(sm + CB0))[n] = bih0[jx] + bhh0[jx];
        ((float*)(sm + CW0))[n] = Wih0[jx];
        ((float*)(sm + CB1))[n] = bih1[jx] + bhh1[jx];
        ((float*)(sm + CBC))[n] = bcih[jx] + bchh[jx];
        ((float*)(sm + CWC))[n] = Wcih[jx];
    }
    if (tid < 16) ((float4*)xbuf)[tid] = __ldg((const float4*)(X + xrow) + tid);
    if (tid < HID) wouts[tid] = Wout[tid];

    float c0st[8], c1st[8];
#pragma unroll
    for (int i = 0; i < 8; ++i) { c0st[i] = 0.f; c1st[i] = 0.f; }

    float d0[4][2][4], d1[4][2][4];
#pragma unroll
    for (int nt = 0; nt < 4; ++nt)
#pragma unroll
        for (int m = 0; m < 2; ++m)
#pragma unroll
            for (int q = 0; q < 4; ++q) d0[nt][m][q] = 0.f;   // L0(0) on h0=0
    __syncthreads();

    // ================= encoder (pipelined, 2 bars/step) =================
    for (int t = 0; t < LL; ++t) {
        // ---- W2(t): epi0 (d0 -> h0new) || L1b (d1 = Whh1 . h1_old) ----
#pragma unroll
        for (int nt = 0; nt < 4; ++nt)
#pragma unroll
            for (int m = 0; m < 2; ++m)
#pragma unroll
                for (int q = 0; q < 4; ++q) d1[nt][m][q] = 0.f;
        epilayer<true>(d0, c0st, cb0, cw0, xbuf + (t & 1) * 64,
                       h0hi, h0lo, u, tg, sb);
        matphaseS(whi, wlo2, h1hi, h1lo, d1, jr, g, tg, sb);
        __syncthreads();   // h0new published; h1_old reads done

        // ---- W1(t): L1a (d1 += Wih1.h0new); L0(t+1) || epi1 (d1 -> h1new)
        matphaseR(aW1i, wlo1, h0hi, h0lo, d1, jr, g, tg, sb);
        if (t + 1 < LL) {
#pragma unroll
            for (int nt = 0; nt < 4; ++nt)
#pragma unroll
                for (int m = 0; m < 2; ++m)
#pragma unroll
                    for (int q = 0; q < 4; ++q) d0[nt][m][q] = 0.f;
            matphaseR(aW0, wlo0, h0hi, h0lo, d0, jr, g, tg, sb);
            if (tid < 16)
                ((float4*)(xbuf + ((t + 1) & 1) * 64))[tid] =
                    __ldg((const float4*)(X + xrow + (long)(t + 1) * SS) + tid);
        }
        epilayer<false>(d1, c1st, cb1, cb1, (const float*)0,
                        h1hi, h1lo, u, tg, sb);
        __syncthreads();   // h1new published
    }

    // ================= decoder =================
    stageW(Wchh, whi, wlo0, tid);
    __syncthreads();
    loadfrags(whi, aW0, jr, g, tg);
    const float bo = __ldg(bout);
    float* xcur = xbuf + 64;               // holds x(LL-1) ((LL-1)&1 == 1)
    __syncthreads();

    for (int dstep = 0; dstep < HOR; ++dstep) {
#pragma unroll
        for (int nt = 0; nt < 4; ++nt)
#pragma unroll
            for (int m = 0; m < 2; ++m)
#pragma unroll
                for (int q = 0; q < 4; ++q) d1[nt][m][q] = 0.f;
        matphaseR(aW0, wlo0, h1hi, h1lo, d1, jr, g, tg, sb);
        __syncthreads();                   // h1_old reads done
        epilayer<true>(d1, c1st, cbc, cwc, xcur, h1hi, h1lo, u, tg, sb);
        __syncthreads();                   // h1new published

        if (tid < MM) {
            const __half* hh = h1hi + tid * HSW;
            const __half* hl = h1lo + tid * HSW;
            float y = bo;
#pragma unroll 8
            for (int k = 0; k < HID; ++k)
                y = fmaf(wouts[k], __half2float(hh[k]) + __half2float(hl[k]), y);
            out[((long)(b * HOR + dstep)) * SS + s0blk + tid] = y;
            xcur[tid] = y;
        }
        __syncthreads();                   // xcur published
    }
}

extern "C" void kernel_launch(void* const* d_in, const int* in_sizes, int n_in,
                              void* d_out, int out_size) {
    const float* X    = (const float*)d_in[0];
    const float* Wih0 = (const float*)d_in[1];
    const float* Whh0 = (const float*)d_in[2];
    const float* bih0 = (const float*)d_in[3];
    const float* bhh0 = (const float*)d_in[4];
    const float* Wih1 = (const float*)d_in[5];
    const float* Whh1 = (const float*)d_in[6];
    const float* bih1 = (const float*)d_in[7];
    const float* bhh1 = (const float*)d_in[8];
    const float* Wcih = (const float*)d_in[9];
    const float* Wchh = (const float*)d_in[10];
    const float* bcih = (const float*)d_in[11];
    const float* bchh = (const float*)d_in[12];
    const float* Wout = (const float*)d_in[13];
    const float* bout = (const float*)d_in[14];

    cudaFuncSetAttribute(lstm_mma_kernel,
                         cudaFuncAttributeMaxDynamicSharedMemorySize, SMEMB);

    lstm_mma_kernel<<<NB, TH, SMEMB>>>(
        X, Wih0, Whh0, bih0, bhh0, Wih1, Whh1, bih1, bhh1,
        Wcih, Wchh, bcih, bchh, Wout, bout, (float*)d_out);
}

// round 16
// speedup vs baseline: 1.1958x; 1.1958x over previous
#include <cuda_runtime.h>
#include <cuda_fp16.h>
#include <cstdint>

// SiteWiseLSTM (sm_103a) — round 12: pipelined HMMA within the register budget.
// TH=256 (255-reg cap). Only ONE fragment set in registers (aW0 = Whh0 hi;
// decoder reloads it with Wchh hi). Wih1-hi / Whh1-hi streamed from SMEM.
// Fixed regs: d0+d1 (128) + aW0 (32) = 160 -> no spill (round 10/11 spilled).
//   W2(t): epi0(d0 -> h0new)                  || L1b: d1 = Whh1.h1old  [SMEM]
//   bar1
//   W1(t): L1a: d1 += Wih1.h0new [SMEM]; L0(t+1): d0 = Whh0.h0new [regs] || epi1
//   bar2
// Math identical to round 9: mma.sync m16n8k16, 3-pass hi/lo fp16 split,
// fp32 accum (rel_err ~1.4e-6).

#define TH   256
#define MM   64
#define HID  64
#define LL   168
#define HOR  24
#define SS   512
#define NB   256
#define HSW  72          // row stride in halves (144B, conflict-free)

// SMEM byte offsets
#define WLO0  0          // [256][72] half : Whh0 lo (decoder: Wchh lo)
#define WLO1  36864      // Wih1 lo
#define WLO2  73728      // Whh1 lo
#define WHIA  110592     // Wih1 hi (also staging for Whh0/Wchh hi)
#define WHIB  147456     // Whh1 hi
#define H0HI  184320     // [64][72] half
#define H0LO  193536
#define H1HI  202752
#define H1LO  211968
#define XB    221184     // float[2][64]
#define WOUTS 221696     // float[64]
#define CB0   221952     // float[256] layer0 bias, [u*4+e]
#define CW0   222976     // float[256] Wih0
#define CB1   224000     // float[256] layer1 bias
#define CBC   225024     // float[256] decoder bias
#define CWC   226048     // float[256] Wcih
#define SMEMB 227072

__device__ __forceinline__ uint32_t lh2(const __half* p) {
    return *(const uint32_t*)p;
}
__device__ __forceinline__ float tanha(float x) {
    float y;
    asm("tanh.approx.f32 %0, %1;" : "=f"(y) : "f"(x));
    return y;
}
__device__ __forceinline__ float sigf(float x) {
    return fmaf(0.5f, tanha(0.5f * x), 0.5f);
}
__device__ __forceinline__ void mma16816(float* d, uint32_t a0, uint32_t a1,
                                         uint32_t a2, uint32_t a3,
                                         uint32_t b0, uint32_t b1) {
    asm volatile(
        "mma.sync.aligned.m16n8k16.row.col.f32.f16.f16.f32 "
        "{%0,%1,%2,%3}, {%4,%5,%6,%7}, {%8,%9}, {%0,%1,%2,%3};"
        : "+f"(d[0]), "+f"(d[1]), "+f"(d[2]), "+f"(d[3])
        : "r"(a0), "r"(a1), "r"(a2), "r"(a3), "r"(b0), "r"(b1));
}

// Stage fp32 W[256][64] (rows e*64+u) -> SMEM hi/lo fp16, permuted rows
// r = 32*(u>>3) + 8*e + (u&7), 72-half stride.
__device__ __forceinline__ void stageW(const float* __restrict__ W,
                                       __half* Hi, __half* Lo, int tid) {
    for (int idx = tid; idx < 256 * 64; idx += TH) {
        int row = idx >> 6, k = idx & 63;
        int e = row >> 6, u = row & 63;
        int r = ((u >> 3) << 5) + (e << 3) + (u & 7);
        float w = W[idx];
        __half hi = __float2half_rn(w);
        __half lo = __float2half_rn(w - __half2float(hi));
        Hi[r * HSW + k] = hi;
        Lo[r * HSW + k] = lo;
    }
}

__device__ __forceinline__ void loadfrags(const __half* Hi, uint32_t (&f)[2][4][4],
                                          int jr, int g, int tg) {
#pragma unroll
    for (int m = 0; m < 2; ++m)
#pragma unroll
        for (int kt = 0; kt < 4; ++kt) {
            int r0 = jr + 16 * m + g, r1 = r0 + 8, kb = 16 * kt + 2 * tg;
            f[m][kt][0] = lh2(Hi + r0 * HSW + kb);
            f[m][kt][1] = lh2(Hi + r1 * HSW + kb);
            f[m][kt][2] = lh2(Hi + r0 * HSW + kb + 8);
            f[m][kt][3] = lh2(Hi + r1 * HSW + kb + 8);
        }
}

// d += (Ahi+Alo).(Bhi) + Ahi.(Blo); A hi fragments from registers.
__device__ __forceinline__ void matphaseR(const uint32_t (&ahi)[2][4][4],
                                          const __half* __restrict__ Alo,
                                          const __half* __restrict__ Bhi,
                                          const __half* __restrict__ Blo,
                                          float (&d)[8][2][4],
                                          int jr, int g, int tg) {
#pragma unroll
    for (int kt = 0; kt < 4; ++kt) {
        const int kb = 16 * kt + 2 * tg;
        uint32_t alo[2][4];
#pragma unroll
        for (int m = 0; m < 2; ++m) {
            int r0 = jr + 16 * m + g, r1 = r0 + 8;
            alo[m][0] = lh2(Alo + r0 * HSW + kb);
            alo[m][1] = lh2(Alo + r1 * HSW + kb);
            alo[m][2] = lh2(Alo + r0 * HSW + kb + 8);
            alo[m][3] = lh2(Alo + r1 * HSW + kb + 8);
        }
#pragma unroll
        for (int nt = 0; nt < 8; ++nt) {
            const __half* bp = Bhi + (8 * nt + g) * HSW + kb;
            uint32_t b0 = lh2(bp), b1 = lh2(bp + 8);
            mma16816(d[nt][0], ahi[0][kt][0], ahi[0][kt][1], ahi[0][kt][2], ahi[0][kt][3], b0, b1);
            mma16816(d[nt][1], ahi[1][kt][0], ahi[1][kt][1], ahi[1][kt][2], ahi[1][kt][3], b0, b1);
            mma16816(d[nt][0], alo[0][0], alo[0][1], alo[0][2], alo[0][3], b0, b1);
            mma16816(d[nt][1], alo[1][0], alo[1][1], alo[1][2], alo[1][3], b0, b1);
        }
#pragma unroll
        for (int nt = 0; nt < 8; ++nt) {
            const __half* bp = Blo + (8 * nt + g) * HSW + kb;
            uint32_t b0 = lh2(bp), b1 = lh2(bp + 8);
            mma16816(d[nt][0], ahi[0][kt][0], ahi[0][kt][1], ahi[0][kt][2], ahi[0][kt][3], b0, b1);
            mma16816(d[nt][1], ahi[1][kt][0], ahi[1][kt][1], ahi[1][kt][2], ahi[1][kt][3], b0, b1);
        }
    }
}

// Same but A hi fragments streamed from SMEM (register relief).
__device__ __forceinline__ void matphaseS(const __half* __restrict__ Ahi,
                                          const __half* __restrict__ Alo,
                                          const __half* __restrict__ Bhi,
                                          const __half* __restrict__ Blo,
                                          float (&d)[8][2][4],
                                          int jr, int g, int tg) {
#pragma unroll
    for (int kt = 0; kt < 4; ++kt) {
        const int kb = 16 * kt + 2 * tg;
        uint32_t ahi[2][4], alo[2][4];
#pragma unroll
        for (int m = 0; m < 2; ++m) {
            int r0 = jr + 16 * m + g, r1 = r0 + 8;
            ahi[m][0] = lh2(Ahi + r0 * HSW + kb);
            ahi[m][1] = lh2(Ahi + r1 * HSW + kb);
            ahi[m][2] = lh2(Ahi + r0 * HSW + kb + 8);
            ahi[m][3] = lh2(Ahi + r1 * HSW + kb + 8);
            alo[m][0] = lh2(Alo + r0 * HSW + kb);
            alo[m][1] = lh2(Alo + r1 * HSW + kb);
            alo[m][2] = lh2(Alo + r0 * HSW + kb + 8);
            alo[m][3] = lh2(Alo + r1 * HSW + kb + 8);
        }
#pragma unroll
        for (int nt = 0; nt < 8; ++nt) {
            const __half* bp = Bhi + (8 * nt + g) * HSW + kb;
            uint32_t b0 = lh2(bp), b1 = lh2(bp + 8);
            mma16816(d[nt][0], ahi[0][0], ahi[0][1], ahi[0][2], ahi[0][3], b0, b1);
            mma16816(d[nt][1], ahi[1][0], ahi[1][1], ahi[1][2], ahi[1][3], b0, b1);
            mma16816(d[nt][0], alo[0][0], alo[0][1], alo[0][2], alo[0][3], b0, b1);
            mma16816(d[nt][1], alo[1][0], alo[1][1], alo[1][2], alo[1][3], b0, b1);
        }
#pragma unroll
        for (int nt = 0; nt < 8; ++nt) {
            const __half* bp = Blo + (8 * nt + g) * HSW + kb;
            uint32_t b0 = lh2(bp), b1 = lh2(bp + 8);
            mma16816(d[nt][0], ahi[0][0], ahi[0][1], ahi[0][2], ahi[0][3], b0, b1);
            mma16816(d[nt][1], ahi[1][0], ahi[1][1], ahi[1][2], ahi[1][3], b0, b1);
        }
    }
}

// Cell update + h writeback for 16 cells (8 nt x 2 samples), unit u.
// d[nt][0][0,1]=i  d[nt][0][2,3]=f  d[nt][1][0,1]=g  d[nt][1][2,3]=o
template<bool HASX>
__device__ __forceinline__ void epilayer(float (&d)[8][2][4], float* cst,
                                         const float4* __restrict__ bs4,
                                         const float4* __restrict__ ws4,
                                         const float* __restrict__ xb,
                                         __half* Hhi, __half* Hlo,
                                         int u, int tg) {
    float4 bb = bs4[u];
    float4 wv = HASX ? ws4[u] : make_float4(0.f, 0.f, 0.f, 0.f);
#pragma unroll
    for (int nt = 0; nt < 8; ++nt) {
        int s0 = 8 * nt + 2 * tg;
        float gi0 = d[nt][0][0] + bb.x, gi1 = d[nt][0][1] + bb.x;
        float gf0 = d[nt][0][2] + bb.y, gf1 = d[nt][0][3] + bb.y;
        float gg0 = d[nt][1][0] + bb.z, gg1 = d[nt][1][1] + bb.z;
        float go0 = d[nt][1][2] + bb.w, go1 = d[nt][1][3] + bb.w;
        if (HASX) {
            float2 xv = *(const float2*)(xb + s0);
            gi0 = fmaf(wv.x, xv.x, gi0); gi1 = fmaf(wv.x, xv.y, gi1);
            gf0 = fmaf(wv.y, xv.x, gf0); gf1 = fmaf(wv.y, xv.y, gf1);
            gg0 = fmaf(wv.z, xv.x, gg0); gg1 = fmaf(wv.z, xv.y, gg1);
            go0 = fmaf(wv.w, xv.x, go0); go1 = fmaf(wv.w, xv.y, go1);
        }
        float nc0 = sigf(gf0) * cst[2 * nt]     + sigf(gi0) * tanha(gg0);
        float nc1 = sigf(gf1) * cst[2 * nt + 1] + sigf(gi1) * tanha(gg1);
        cst[2 * nt] = nc0; cst[2 * nt + 1] = nc1;
        float h0 = sigf(go0) * tanha(nc0);
        float h1 = sigf(go1) * tanha(nc1);
        __half hh0 = __float2half_rn(h0);
        __half hh1 = __float2half_rn(h1);
        Hhi[s0 * HSW + u] = hh0;
        Hlo[s0 * HSW + u] = __float2half_rn(h0 - __half2float(hh0));
        Hhi[(s0 + 1) * HSW + u] = hh1;
        Hlo[(s0 + 1) * HSW + u] = __float2half_rn(h1 - __half2float(hh1));
    }
}

__global__ void __launch_bounds__(TH, 1)
lstm_mma_kernel(const float* __restrict__ X,
                const float* __restrict__ Wih0, const float* __restrict__ Whh0,
                const float* __restrict__ bih0, const float* __restrict__ bhh0,
                const float* __restrict__ Wih1, const float* __restrict__ Whh1,
                const float* __restrict__ bih1, const float* __restrict__ bhh1,
                const float* __restrict__ Wcih, const float* __restrict__ Wchh,
                const float* __restrict__ bcih, const float* __restrict__ bchh,
                const float* __restrict__ Wout, const float* __restrict__ bout,
                float* __restrict__ out) {
    extern __shared__ char sm[];
    __half* wlo0 = (__half*)(sm + WLO0);
    __half* wlo1 = (__half*)(sm + WLO1);
    __half* wlo2 = (__half*)(sm + WLO2);
    __half* whiA = (__half*)(sm + WHIA);
    __half* whiB = (__half*)(sm + WHIB);
    __half* h0hi = (__half*)(sm + H0HI);
    __half* h0lo = (__half*)(sm + H0LO);
    __half* h1hi = (__half*)(sm + H1HI);
    __half* h1lo = (__half*)(sm + H1LO);
    float* xbuf  = (float*)(sm + XB);
    float* wouts = (float*)(sm + WOUTS);
    const float4* cb0 = (const float4*)(sm + CB0);
    const float4* cw0 = (const float4*)(sm + CW0);
    const float4* cb1 = (const float4*)(sm + CB1);
    const float4* cbc = (const float4*)(sm + CBC);
    const float4* cwc = (const float4*)(sm + CWC);

    const int tid = threadIdx.x;
    const int lane = tid & 31;
    const int j = tid >> 5;
    const int g = lane >> 2;
    const int tg = lane & 3;
    const int jr = 32 * j;
    const int u = 8 * j + g;

    const int n0 = blockIdx.x * MM;
    const int b  = n0 >> 9;
    const int s0blk = n0 & (SS - 1);
    const long xrow = (long)b * LL * SS + s0blk;

    uint32_t aW0[2][4][4];   // Whh0 hi (decoder: Wchh hi) — the ONLY reg frags

    // ---- stage weights: Whh0 hi via whiA staging -> regs; others in SMEM ----
    stageW(Whh0, whiA, wlo0, tid);
    __syncthreads();
    loadfrags(whiA, aW0, jr, g, tg);
    __syncthreads();
    stageW(Wih1, whiA, wlo1, tid);         // Wih1 hi stays in whiA
    stageW(Whh1, whiB, wlo2, tid);         // Whh1 hi stays in whiB

    // zero h arrays, stage constants / x(0) / wout
    for (int idx = tid; idx < (4 * 9216) / 4; idx += TH)
        ((uint32_t*)(sm + H0HI))[idx] = 0;
    for (int jx = tid; jx < 256; jx += TH) {
        int e = jx >> 6, uu = jx & 63, n = uu * 4 + e;
        ((float*)(sm + CB0))[n] = bih0[jx] + bhh0[jx];
        ((float*)(sm + CW0))[n] = Wih0[jx];
        ((float*)(sm + CB1))[n] = bih1[jx] + bhh1[jx];
        ((float*)(sm + CBC))[n] = bcih[jx] + bchh[jx];
        ((float*)(sm + CWC))[n] = Wcih[jx];
    }
    if (tid < 16) ((float4*)xbuf)[tid] = __ldg((const float4*)(X + xrow) + tid);
    if (tid < HID) wouts[tid] = Wout[tid];

    float c0st[16], c1st[16];
#pragma unroll
    for (int i = 0; i < 16; ++i) { c0st[i] = 0.f; c1st[i] = 0.f; }

    float d0[8][2][4], d1[8][2][4];
#pragma unroll
    for (int nt = 0; nt < 8; ++nt)
#pragma unroll
        for (int m = 0; m < 2; ++m)
#pragma unroll
            for (int q = 0; q < 4; ++q) d0[nt][m][q] = 0.f;   // L0(0) on h0=0
    __syncthreads();

    // ================= encoder (pipelined, 2 bars/step) =================
    for (int t = 0; t < LL; ++t) {
        // ---- W2(t): epi0 (d0 -> h0new) || L1b (d1 = Whh1 . h1_old, SMEM) --
#pragma unroll
        for (int nt = 0; nt < 8; ++nt)
#pragma unroll
            for (int m = 0; m < 2; ++m)
#pragma unroll
                for (int q = 0; q < 4; ++q) d1[nt][m][q] = 0.f;
        epilayer<true>(d0, c0st, cb0, cw0, xbuf + (t & 1) * 64,
                       h0hi, h0lo, u, tg);
        matphaseS(whiB, wlo2, h1hi, h1lo, d1, jr, g, tg);
        __syncthreads();   // h0new published; h1_old reads done

        // ---- W1(t): L1a (SMEM); L0(t+1) (regs) || epi1 (d1 -> h1new) ----
        matphaseS(whiA, wlo1, h0hi, h0lo, d1, jr, g, tg);
        if (t + 1 < LL) {
#pragma unroll
            for (int nt = 0; nt < 8; ++nt)
#pragma unroll
                for (int m = 0; m < 2; ++m)
#pragma unroll
                    for (int q = 0; q < 4; ++q) d0[nt][m][q] = 0.f;
            matphaseR(aW0, wlo0, h0hi, h0lo, d0, jr, g, tg);
            if (tid < 16)
                ((float4*)(xbuf + ((t + 1) & 1) * 64))[tid] =
                    __ldg((const float4*)(X + xrow + (long)(t + 1) * SS) + tid);
        }
        epilayer<false>(d1, c1st, cb1, cb1, (const float*)0,
                        h1hi, h1lo, u, tg);
        __syncthreads();   // h1new published
    }

    // ================= decoder =================
    stageW(Wchh, whiA, wlo0, tid);
    __syncthreads();
    loadfrags(whiA, aW0, jr, g, tg);
    const float bo = __ldg(bout);
    float* xcur = xbuf + 64;               // holds x(LL-1) ((LL-1)&1 == 1)
    __syncthreads();

    for (int dstep = 0; dstep < HOR; ++dstep) {
#pragma unroll
        for (int nt = 0; nt < 8; ++nt)
#pragma unroll
            for (int m = 0; m < 2; ++m)
#pragma unroll
                for (int q = 0; q < 4; ++q) d1[nt][m][q] = 0.f;
        matphaseR(aW0, wlo0, h1hi, h1lo, d1, jr, g, tg);
        __syncthreads();                   // h1_old reads done
        epilayer<true>(d1, c1st, cbc, cwc, xcur, h1hi, h1lo, u, tg);
        __syncthreads();                   // h1new published

        if (tid < MM) {
            const __half* hh = h1hi + tid * HSW;
            const __half* hl = h1lo + tid * HSW;
            float y = bo;
#pragma unroll 8
            for (int k = 0; k < HID; ++k)
                y = fmaf(wouts[k], __half2float(hh[k]) + __half2float(hl[k]), y);
            out[((long)(b * HOR + dstep)) * SS + s0blk + tid] = y;
            xcur[tid] = y;
        }
        __syncthreads();                   // xcur published
    }
}

extern "C" void kernel_launch(void* const* d_in, const int* in_sizes, int n_in,
                              void* d_out, int out_size) {
    const float* X    = (const float*)d_in[0];
    const float* Wih0 = (const float*)d_in[1];
    const float* Whh0 = (const float*)d_in[2];
    const float* bih0 = (const float*)d_in[3];
    const float* bhh0 = (const float*)d_in[4];
    const float* Wih1 = (const float*)d_in[5];
    const float* Whh1 = (const float*)d_in[6];
    const float* bih1 = (const float*)d_in[7];
    const float* bhh1 = (const float*)d_in[8];
    const float* Wcih = (const float*)d_in[9];
    const float* Wchh = (const float*)d_in[10];
    const float* bcih = (const float*)d_in[11];
    const float* bchh = (const float*)d_in[12];
    const float* Wout = (const float*)d_in[13];
    const float* bout = (const float*)d_in[14];

    cudaFuncSetAttribute(lstm_mma_kernel,
                         cudaFuncAttributeMaxDynamicSharedMemorySize, SMEMB);

    lstm_mma_kernel<<<NB, TH, SMEMB>>>(
        X, Wih0, Whh0, bih0, bhh0, Wih1, Whh1, bih1, bhh1,
        Wcih, Wchh, bcih, bchh, Wout, bout, (float*)d_out);
}

// round 17
// speedup vs baseline: 1.7642x; 1.4753x over previous
#include <cuda_runtime.h>
#include <cuda_fp16.h>
#include <cstdint>

// SiteWiseLSTM (sm_103a) — round 13: pipelined HMMA, 2-pass split, fits regs.
// Changes vs round 12:
//  - h stored as plain fp16 (no lo plane): MMA passes 3 -> 2 (-33% tensor
//    work), shorter epilogue, halved h SMEM, fewer live temps.
//  - W still split hi+lo fp16 (exact to 2^-22); predicted rel_err ~1e-4.
// Pipeline (2 bars/step), every epilogue overlapped with an independent MMA:
//   W2(t): epi0(d0 -> h0new)                 || L1b: d1 = Whh1.h1old [SMEM]
//   bar1
//   W1(t): L1a: d1 += Wih1.h0new [SMEM]; L0(t+1): d0 = Whh0.h0new [regs] || epi1
//   bar2
// Fixed regs: d0+d1 (128) + aW0 (32) + c (32) = 192; temps ~40 -> no spill.

#define TH   256
#define MM   64
#define HID  64
#define LL   168
#define HOR  24
#define SS   512
#define NB   256
#define HSW  72          // row stride in halves (144B; 4g+tg bank pattern, conflict-free)

// SMEM byte offsets
#define WLO0  0          // [256][72] half : Whh0 lo (decoder: Wchh lo)
#define WLO1  36864      // Wih1 lo
#define WLO2  73728      // Whh1 lo
#define WHIA  110592     // Wih1 hi (also staging for Whh0/Wchh hi)
#define WHIB  147456     // Whh1 hi
#define H0P   184320     // [64][72] half (fp16 h0)
#define H1P   193536     // [64][72] half (fp16 h1)
#define XB    202752     // float[2][64]
#define WOUTS 203264     // float[64]
#define CB0   203520     // float[256] layer0 bias, [u*4+e]
#define CW0   204544     // float[256] Wih0
#define CB1   205568     // float[256] layer1 bias
#define CBC   206592     // float[256] decoder bias
#define CWC   207616     // float[256] Wcih
#define SMEMB 208640

__device__ __forceinline__ uint32_t lh2(const __half* p) {
    return *(const uint32_t*)p;
}
__device__ __forceinline__ float tanha(float x) {
    float y;
    asm("tanh.approx.f32 %0, %1;" : "=f"(y) : "f"(x));
    return y;
}
__device__ __forceinline__ float sigf(float x) {
    return fmaf(0.5f, tanha(0.5f * x), 0.5f);
}
__device__ __forceinline__ void mma16816(float* d, uint32_t a0, uint32_t a1,
                                         uint32_t a2, uint32_t a3,
                                         uint32_t b0, uint32_t b1) {
    asm volatile(
        "mma.sync.aligned.m16n8k16.row.col.f32.f16.f16.f32 "
        "{%0,%1,%2,%3}, {%4,%5,%6,%7}, {%8,%9}, {%0,%1,%2,%3};"
        : "+f"(d[0]), "+f"(d[1]), "+f"(d[2]), "+f"(d[3])
        : "r"(a0), "r"(a1), "r"(a2), "r"(a3), "r"(b0), "r"(b1));
}

// Stage fp32 W[256][64] (rows e*64+u) -> SMEM hi/lo fp16, permuted rows
// r = 32*(u>>3) + 8*e + (u&7), 72-half stride.
__device__ __forceinline__ void stageW(const float* __restrict__ W,
                                       __half* Hi, __half* Lo, int tid) {
    for (int idx = tid; idx < 256 * 64; idx += TH) {
        int row = idx >> 6, k = idx & 63;
        int e = row >> 6, u = row & 63;
        int r = ((u >> 3) << 5) + (e << 3) + (u & 7);
        float w = W[idx];
        __half hi = __float2half_rn(w);
        __half lo = __float2half_rn(w - __half2float(hi));
        Hi[r * HSW + k] = hi;
        Lo[r * HSW + k] = lo;
    }
}

__device__ __forceinline__ void loadfrags(const __half* Hi, uint32_t (&f)[2][4][4],
                                          int jr, int g, int tg) {
#pragma unroll
    for (int m = 0; m < 2; ++m)
#pragma unroll
        for (int kt = 0; kt < 4; ++kt) {
            int r0 = jr + 16 * m + g, r1 = r0 + 8, kb = 16 * kt + 2 * tg;
            f[m][kt][0] = lh2(Hi + r0 * HSW + kb);
            f[m][kt][1] = lh2(Hi + r1 * HSW + kb);
            f[m][kt][2] = lh2(Hi + r0 * HSW + kb + 8);
            f[m][kt][3] = lh2(Hi + r1 * HSW + kb + 8);
        }
}

// 2-pass: d += Ahi.B + Alo.B ; A hi fragments from registers, B = fp16 h.
__device__ __forceinline__ void matphaseR(const uint32_t (&ahi)[2][4][4],
                                          const __half* __restrict__ Alo,
                                          const __half* __restrict__ B,
                                          float (&d)[8][2][4],
                                          int jr, int g, int tg) {
#pragma unroll
    for (int kt = 0; kt < 4; ++kt) {
        const int kb = 16 * kt + 2 * tg;
        uint32_t alo[2][4];
#pragma unroll
        for (int m = 0; m < 2; ++m) {
            int r0 = jr + 16 * m + g, r1 = r0 + 8;
            alo[m][0] = lh2(Alo + r0 * HSW + kb);
            alo[m][1] = lh2(Alo + r1 * HSW + kb);
            alo[m][2] = lh2(Alo + r0 * HSW + kb + 8);
            alo[m][3] = lh2(Alo + r1 * HSW + kb + 8);
        }
#pragma unroll
        for (int nt = 0; nt < 8; ++nt) {
            const __half* bp = B + (8 * nt + g) * HSW + kb;
            uint32_t b0 = lh2(bp), b1 = lh2(bp + 8);
            mma16816(d[nt][0], ahi[0][kt][0], ahi[0][kt][1], ahi[0][kt][2], ahi[0][kt][3], b0, b1);
            mma16816(d[nt][1], ahi[1][kt][0], ahi[1][kt][1], ahi[1][kt][2], ahi[1][kt][3], b0, b1);
            mma16816(d[nt][0], alo[0][0], alo[0][1], alo[0][2], alo[0][3], b0, b1);
            mma16816(d[nt][1], alo[1][0], alo[1][1], alo[1][2], alo[1][3], b0, b1);
        }
    }
}

// Same but A hi fragments streamed from SMEM.
__device__ __forceinline__ void matphaseS(const __half* __restrict__ Ahi,
                                          const __half* __restrict__ Alo,
                                          const __half* __restrict__ B,
                                          float (&d)[8][2][4],
                                          int jr, int g, int tg) {
#pragma unroll
    for (int kt = 0; kt < 4; ++kt) {
        const int kb = 16 * kt + 2 * tg;
        uint32_t ahi[2][4], alo[2][4];
#pragma unroll
        for (int m = 0; m < 2; ++m) {
            int r0 = jr + 16 * m + g, r1 = r0 + 8;
            ahi[m][0] = lh2(Ahi + r0 * HSW + kb);
            ahi[m][1] = lh2(Ahi + r1 * HSW + kb);
            ahi[m][2] = lh2(Ahi + r0 * HSW + kb + 8);
            ahi[m][3] = lh2(Ahi + r1 * HSW + kb + 8);
            alo[m][0] = lh2(Alo + r0 * HSW + kb);
            alo[m][1] = lh2(Alo + r1 * HSW + kb);
            alo[m][2] = lh2(Alo + r0 * HSW + kb + 8);
            alo[m][3] = lh2(Alo + r1 * HSW + kb + 8);
        }
#pragma unroll
        for (int nt = 0; nt < 8; ++nt) {
            const __half* bp = B + (8 * nt + g) * HSW + kb;
            uint32_t b0 = lh2(bp), b1 = lh2(bp + 8);
            mma16816(d[nt][0], ahi[0][0], ahi[0][1], ahi[0][2], ahi[0][3], b0, b1);
            mma16816(d[nt][1], ahi[1][0], ahi[1][1], ahi[1][2], ahi[1][3], b0, b1);
            mma16816(d[nt][0], alo[0][0], alo[0][1], alo[0][2], alo[0][3], b0, b1);
            mma16816(d[nt][1], alo[1][0], alo[1][1], alo[1][2], alo[1][3], b0, b1);
        }
    }
}

// Cell update + fp16 h writeback for 16 cells (8 nt x 2 samples), unit u.
// d[nt][0][0,1]=i  d[nt][0][2,3]=f  d[nt][1][0,1]=g  d[nt][1][2,3]=o
template<bool HASX>
__device__ __forceinline__ void epilayer(float (&d)[8][2][4], float* cst,
                                         const float4* __restrict__ bs4,
                                         const float4* __restrict__ ws4,
                                         const float* __restrict__ xb,
                                         __half* Hp, int u, int tg) {
    float4 bb = bs4[u];
    float4 wv = HASX ? ws4[u] : make_float4(0.f, 0.f, 0.f, 0.f);
#pragma unroll
    for (int nt = 0; nt < 8; ++nt) {
        int s0 = 8 * nt + 2 * tg;
        float gi0 = d[nt][0][0] + bb.x, gi1 = d[nt][0][1] + bb.x;
        float gf0 = d[nt][0][2] + bb.y, gf1 = d[nt][0][3] + bb.y;
        float gg0 = d[nt][1][0] + bb.z, gg1 = d[nt][1][1] + bb.z;
        float go0 = d[nt][1][2] + bb.w, go1 = d[nt][1][3] + bb.w;
        if (HASX) {
            float2 xv = *(const float2*)(xb + s0);
            gi0 = fmaf(wv.x, xv.x, gi0); gi1 = fmaf(wv.x, xv.y, gi1);
            gf0 = fmaf(wv.y, xv.x, gf0); gf1 = fmaf(wv.y, xv.y, gf1);
            gg0 = fmaf(wv.z, xv.x, gg0); gg1 = fmaf(wv.z, xv.y, gg1);
            go0 = fmaf(wv.w, xv.x, go0); go1 = fmaf(wv.w, xv.y, go1);
        }
        float nc0 = sigf(gf0) * cst[2 * nt]     + sigf(gi0) * tanha(gg0);
        float nc1 = sigf(gf1) * cst[2 * nt + 1] + sigf(gi1) * tanha(gg1);
        cst[2 * nt] = nc0; cst[2 * nt + 1] = nc1;
        float h0 = sigf(go0) * tanha(nc0);
        float h1 = sigf(go1) * tanha(nc1);
        Hp[s0 * HSW + u]       = __float2half_rn(h0);
        Hp[(s0 + 1) * HSW + u] = __float2half_rn(h1);
    }
}

__global__ void __launch_bounds__(TH, 1)
lstm_mma_kernel(const float* __restrict__ X,
                const float* __restrict__ Wih0, const float* __restrict__ Whh0,
                const float* __restrict__ bih0, const float* __restrict__ bhh0,
                const float* __restrict__ Wih1, const float* __restrict__ Whh1,
                const float* __restrict__ bih1, const float* __restrict__ bhh1,
                const float* __restrict__ Wcih, const float* __restrict__ Wchh,
                const float* __restrict__ bcih, const float* __restrict__ bchh,
                const float* __restrict__ Wout, const float* __restrict__ bout,
                float* __restrict__ out) {
    extern __shared__ char sm[];
    __half* wlo0 = (__half*)(sm + WLO0);
    __half* wlo1 = (__half*)(sm + WLO1);
    __half* wlo2 = (__half*)(sm + WLO2);
    __half* whiA = (__half*)(sm + WHIA);
    __half* whiB = (__half*)(sm + WHIB);
    __half* h0p  = (__half*)(sm + H0P);
    __half* h1p  = (__half*)(sm + H1P);
    float* xbuf  = (float*)(sm + XB);
    float* wouts = (float*)(sm + WOUTS);
    const float4* cb0 = (const float4*)(sm + CB0);
    const float4* cw0 = (const float4*)(sm + CW0);
    const float4* cb1 = (const float4*)(sm + CB1);
    const float4* cbc = (const float4*)(sm + CBC);
    const float4* cwc = (const float4*)(sm + CWC);

    const int tid = threadIdx.x;
    const int lane = tid & 31;
    const int j = tid >> 5;
    const int g = lane >> 2;
    const int tg = lane & 3;
    const int jr = 32 * j;
    const int u = 8 * j + g;

    const int n0 = blockIdx.x * MM;
    const int b  = n0 >> 9;
    const int s0blk = n0 & (SS - 1);
    const long xrow = (long)b * LL * SS + s0blk;

    uint32_t aW0[2][4][4];   // Whh0 hi (decoder: Wchh hi) — the ONLY reg frags

    // ---- stage weights: Whh0 hi via whiA staging -> regs; others in SMEM ----
    stageW(Whh0, whiA, wlo0, tid);
    __syncthreads();
    loadfrags(whiA, aW0, jr, g, tg);
    __syncthreads();
    stageW(Wih1, whiA, wlo1, tid);         // Wih1 hi stays in whiA
    stageW(Whh1, whiB, wlo2, tid);         // Whh1 hi stays in whiB

    // zero h planes, stage constants / x(0) / wout
    for (int idx = tid; idx < (2 * 9216) / 4; idx += TH)
        ((uint32_t*)(sm + H0P))[idx] = 0;
    for (int jx = tid; jx < 256; jx += TH) {
        int e = jx >> 6, uu = jx & 63, n = uu * 4 + e;
        ((float*)(sm + CB0))[n] = bih0[jx] + bhh0[jx];
        ((float*)(sm + CW0))[n] = Wih0[jx];
        ((float*)(sm + CB1))[n] = bih1[jx] + bhh1[jx];
        ((float*)(sm + CBC))[n] = bcih[jx] + bchh[jx];
        ((float*)(sm + CWC))[n] = Wcih[jx];
    }
    if (tid < 16) ((float4*)xbuf)[tid] = __ldg((const float4*)(X + xrow) + tid);
    if (tid < HID) wouts[tid] = Wout[tid];

    float c0st[16], c1st[16];
#pragma unroll
    for (int i = 0; i < 16; ++i) { c0st[i] = 0.f; c1st[i] = 0.f; }

    float d0[8][2][4], d1[8][2][4];
#pragma unroll
    for (int nt = 0; nt < 8; ++nt)
#pragma unroll
        for (int m = 0; m < 2; ++m)
#pragma unroll
            for (int q = 0; q < 4; ++q) d0[nt][m][q] = 0.f;   // L0(0) on h0=0
    __syncthreads();

    // ================= encoder (pipelined, 2 bars/step) =================
    for (int t = 0; t < LL; ++t) {
        // ---- W2(t): epi0 (d0 -> h0new) || L1b (d1 = Whh1 . h1_old, SMEM) --
#pragma unroll
        for (int nt = 0; nt < 8; ++nt)
#pragma unroll
            for (int m = 0; m < 2; ++m)
#pragma unroll
                for (int q = 0; q < 4; ++q) d1[nt][m][q] = 0.f;
        epilayer<true>(d0, c0st, cb0, cw0, xbuf + (t & 1) * 64, h0p, u, tg);
        matphaseS(whiB, wlo2, h1p, d1, jr, g, tg);
        __syncthreads();   // h0new published; h1_old reads done

        // ---- W1(t): L1a (SMEM); L0(t+1) (regs) || epi1 (d1 -> h1new) ----
        matphaseS(whiA, wlo1, h0p, d1, jr, g, tg);
        if (t + 1 < LL) {
#pragma unroll
            for (int nt = 0; nt < 8; ++nt)
#pragma unroll
                for (int m = 0; m < 2; ++m)
#pragma unroll
                    for (int q = 0; q < 4; ++q) d0[nt][m][q] = 0.f;
            matphaseR(aW0, wlo0, h0p, d0, jr, g, tg);
            if (tid < 16)
                ((float4*)(xbuf + ((t + 1) & 1) * 64))[tid] =
                    __ldg((const float4*)(X + xrow + (long)(t + 1) * SS) + tid);
        }
        epilayer<false>(d1, c1st, cb1, cb1, (const float*)0, h1p, u, tg);
        __syncthreads();   // h1new published
    }

    // ================= decoder =================
    stageW(Wchh, whiA, wlo0, tid);         // Wih1 planes dead; reuse whiA staging
    __syncthreads();
    loadfrags(whiA, aW0, jr, g, tg);
    const float bo = __ldg(bout);
    float* xcur = xbuf + 64;               // holds x(LL-1) ((LL-1)&1 == 1)
    __syncthreads();

    for (int dstep = 0; dstep < HOR; ++dstep) {
#pragma unroll
        for (int nt = 0; nt < 8; ++nt)
#pragma unroll
            for (int m = 0; m < 2; ++m)
#pragma unroll
                for (int q = 0; q < 4; ++q) d1[nt][m][q] = 0.f;
        matphaseR(aW0, wlo0, h1p, d1, jr, g, tg);
        __syncthreads();                   // h1_old reads done
        epilayer<true>(d1, c1st, cbc, cwc, xcur, h1p, u, tg);
        __syncthreads();                   // h1new published

        if (tid < MM) {
            const __half* hp = h1p + tid * HSW;
            float y = bo;
#pragma unroll 8
            for (int k = 0; k < HID; ++k)
                y = fmaf(wouts[k], __half2float(hp[k]), y);
            out[((long)(b * HOR + dstep)) * SS + s0blk + tid] = y;
            xcur[tid] = y;
        }
        __syncthreads();                   // xcur published
    }
}

extern "C" void kernel_launch(void* const* d_in, const int* in_sizes, int n_in,
                              void* d_out, int out_size) {
    const float* X    = (const float*)d_in[0];
    const float* Wih0 = (const float*)d_in[1];
    const float* Whh0 = (const float*)d_in[2];
    const float* bih0 = (const float*)d_in[3];
    const float* bhh0 = (const float*)d_in[4];
    const float* Wih1 = (const float*)d_in[5];
    const float* Whh1 = (const float*)d_in[6];
    const float* bih1 = (const float*)d_in[7];
    const float* bhh1 = (const float*)d_in[8];
    const float* Wcih = (const float*)d_in[9];
    const float* Wchh = (const float*)d_in[10];
    const float* bcih = (const float*)d_in[11];
    const float* bchh = (const float*)d_in[12];
    const float* Wout = (const float*)d_in[13];
    const float* bout = (const float*)d_in[14];

    cudaFuncSetAttribute(lstm_mma_kernel,
                         cudaFuncAttributeMaxDynamicSharedMemorySize, SMEMB);

    lstm_mma_kernel<<<NB, TH, SMEMB>>>(
        X, Wih0, Whh0, bih0, bhh0, Wih1, Whh1, bih1, bhh1,
        Wcih, Wchh, bcih, bchh, Wout, bout, (float*)d_out);
}